// round 11
// baseline (speedup 1.0000x reference)
#include <cuda_runtime.h>
#include <cstdint>

// Problem constants
#define Bn 4
#define Tn 64
#define Fn 32
#define Nn 512
#define Hn 64
#define SROWS 288
#define COLS_PER_CTA 16
#define CTAS_PER_B 32
#define NCTAS (Bn * CTAS_PER_B)   // 128 CTAs, 1/SM
#define NTHREADS 512
#define MB 32                     // k-chunk width
#define NCHUNK (Nn / MB)          // 16
#define RPT 9

#define CPITCH 36                 // chunk row pitch: banks 4*RG mod 32 distinct
#define PITCH_SST 260             // S^T half pitch: 256 k + 4 pad
#define SST_HALF 256
#define PITCH_V  388
#define NV       384
#define PITCH_YP 18

#define CHUNK_FLOATS (SROWS * CPITCH)      // 10368
#define CHUNK_BYTES  (CHUNK_FLOATS * 4)    // 41472

// smem layout (float offsets) — identical to R10
#define OFF_W      0                        // 64*384 = 24576
#define OFF_BIAS   24576                    // 64
#define OFF_MBAR   24640                    // 4 (2 x 8B mbarriers)
#define OFF_STATE  24644                    // 2*10368 = 20736
#define OFF_SST    45380                    // union: S^T half (16*260=4160) / sYp (288*18=5184)
#define OFF_V      50564                    // 16*388 = 6208
#define SMEM_FLOATS 56772
#define SMEM_BYTES  (SMEM_FLOATS * 4)       // 227088 <= 232448

// Persistent global state: chunk-major, rows pre-padded to CPITCH floats.
__device__ __align__(16) float g_state[2][Bn][NCHUNK][SROWS][CPITCH];
__device__ unsigned g_count = 0;
__device__ unsigned g_sense = 0;

__device__ __forceinline__ void grid_barrier(unsigned* lsense) {
    __syncthreads();
    if (threadIdx.x == 0) {
        __threadfence();
        unsigned s = (*lsense) ^ 1u;
        *lsense = s;
        unsigned old = atomicAdd(&g_count, 1u);
        if (old == NCTAS - 1u) {
            atomicExch(&g_count, 0u);
            __threadfence();
            atomicExch(&g_sense, s);
        } else {
            while (atomicAdd(&g_sense, 0u) != s) { __nanosleep(64); }
            __threadfence();
        }
    }
    __syncthreads();
}

__device__ __forceinline__ unsigned long long ffma2(unsigned long long a,
                                                    unsigned long long b,
                                                    unsigned long long c) {
    unsigned long long d;
    asm("fma.rn.f32x2 %0, %1, %2, %3;" : "=l"(d) : "l"(a), "l"(b), "l"(c));
    return d;
}
__device__ __forceinline__ float upsum(unsigned long long p) {
    float lo, hi;
    asm("mov.b64 {%0, %1}, %2;" : "=f"(lo), "=f"(hi) : "l"(p));
    return lo + hi;
}

// mbarrier helpers
__device__ __forceinline__ void mbar_init(uint32_t addr, uint32_t count) {
    asm volatile("mbarrier.init.shared.b64 [%0], %1;" :: "r"(addr), "r"(count) : "memory");
}
__device__ __forceinline__ void mbar_expect_tx(uint32_t addr, uint32_t bytes) {
    asm volatile("mbarrier.arrive.expect_tx.shared.b64 _, [%0], %1;"
                 :: "r"(addr), "r"(bytes) : "memory");
}
__device__ __forceinline__ void mbar_wait(uint32_t addr, uint32_t parity) {
    uint32_t done;
    asm volatile(
        "{\n\t.reg .pred p;\n\t"
        "mbarrier.try_wait.parity.acquire.cta.shared::cta.b64 p, [%1], %2;\n\t"
        "selp.b32 %0, 1, 0, p;\n\t}"
        : "=r"(done) : "r"(addr), "r"(parity) : "memory");
    if (!done) {
        asm volatile(
            "{\n\t.reg .pred P1;\n\t"
            "WL_%=:\n\t"
            "mbarrier.try_wait.parity.acquire.cta.shared::cta.b64 P1, [%0], %1, 0x989680;\n\t"
            "@P1 bra.uni WD_%=;\n\t"
            "bra.uni WL_%=;\n\t"
            "WD_%=:\n\t}"
            :: "r"(addr), "r"(parity) : "memory");
    }
}
__device__ __forceinline__ void bulk_copy(uint32_t dst_smem, const void* src, uint32_t bytes,
                                          uint32_t mbar) {
    asm volatile(
        "cp.async.bulk.shared::cta.global.mbarrier::complete_tx::bytes [%0], [%1], %2, [%3];"
        :: "r"(dst_smem), "l"(src), "r"(bytes), "r"(mbar) : "memory");
}

__global__ void __launch_bounds__(NTHREADS, 1)
hs_db_kernel(const float* __restrict__ x,      // (B,T,F,N)
             const float* __restrict__ z0,     // (B,H,N)
             const float* __restrict__ S,      // (B,T,1,N,N)
             const float* __restrict__ aW,     // (H,1,K,F)
             const float* __restrict__ bW,     // (H,1,K,H)
             const float* __restrict__ xBias,  // (H,1)
             const float* __restrict__ zBias,  // (H,1)
             float* __restrict__ out)          // (B,T,H,N)
{
    extern __shared__ float sm[];
    float* sW    = sm + OFF_W;
    float* sbias = sm + OFF_BIAS;
    float* sST   = sm + OFF_SST;    // S^T half buffer (aliased by sYp after k-loop)
    float* sYp   = sm + OFF_SST;    // partial-Y reduction buffer (same region)
    float* sV    = sm + OFF_V;

    const int tid  = threadIdx.x;
    const int b    = blockIdx.x / CTAS_PER_B;
    const int col0 = (blockIdx.x % CTAS_PER_B) * COLS_PER_CTA;
    const int kc0  = col0 >> 5;           // this CTA's write chunk
    const int cmb  = col0 & 31;           // 0 or 16 within chunk

    // phase-1 mapping: 4 k-groups of 128 threads; tile = 9 rows x 4 cols
    const int kg   = tid >> 7;            // 0..3: k-quarter within chunk [8*kg, 8*kg+8)
    const int t128 = tid & 127;
    const int cgp  = t128 & 3;            // cols {cgp, cgp+4, cgp+8, cgp+12}
    const int RG   = t128 >> 2;           // 0..31
    const int R0   = RG * RPT;
    // phase-2 mapping: thread -> (2 h, 1 col)
    const int h2  = tid >> 4;             // 0..31; h in {h2, h2+32}
    const int cc2 = tid & 15;
    // S^T staging mapping: thread -> (k-row tid>>1, col half tid&1)
    const int skrow = tid >> 1;
    const int scol0 = 8 * (tid & 1);

    const uint32_t smem_u32 = (uint32_t)__cvta_generic_to_shared(sm);
    const uint32_t mbar0 = smem_u32 + OFF_MBAR * 4;
    const uint32_t mbar1 = mbar0 + 8;
    const uint32_t st_smem0 = smem_u32 + OFF_STATE * 4;
    const uint32_t st_smem1 = st_smem0 + CHUNK_BYTES;

    if (tid == 0) { mbar_init(mbar0, 1); mbar_init(mbar1, 1); }

    // Load fused weights once: sW[h][0..127]=aW[h], [128..383]=bW[h]
    for (int i = tid; i < Hn * 128; i += NTHREADS) {
        int h = i >> 7, j = i & 127;
        sW[h * NV + j] = aW[i];
    }
    for (int i = tid; i < Hn * 256; i += NTHREADS) {
        int h = i >> 8, j = i & 255;
        sW[h * NV + 128 + j] = bW[i];
    }
    if (tid < Hn) sbias[tid] = xBias[tid] + zBias[tid];

    // Init: zero this CTA's state columns; sV z-region <- z0
    for (int i = tid; i < SROWS * COLS_PER_CTA; i += NTHREADS) {
        int r = i >> 4, cc = i & 15;
        g_state[0][b][kc0][r][cmb + cc] = 0.0f;
    }
    for (int i = tid; i < Hn * COLS_PER_CTA; i += NTHREADS) {
        int g = i >> 4, cc = i & 15;
        sV[cc * PITCH_V + 128 + g] = z0[(b * Hn + g) * Nn + col0 + cc];
    }

    unsigned lsense = 0;
    unsigned ph0 = 0, ph1 = 0;
    grid_barrier(&lsense);   // barrier #1 (orders mbarrier init + state zero)

    for (int t = 0; t < Tn; ++t) {
        const int cur = t & 1;
        const int nxt = cur ^ 1;
        const float* Sbt = S + (size_t)(b * Tn + t) * Nn * Nn;
        const float* xbt = x + (size_t)(b * Tn + t) * Fn * Nn;
        const float* gst = &g_state[cur][b][0][0][0];

        // prologue: launch TMA for chunk 0 immediately
        if (tid == 0) {
            mbar_expect_tx(mbar0, CHUNK_BYTES);
            bulk_copy(st_smem0, gst, CHUNK_BYTES, mbar0);
        }

        // Stage x(t) -> sV[cc][0..31]  (one element per thread)
        {
            int f = tid >> 4, cc = tid & 15;
            sV[cc * PITCH_V + f] = xbt[f * Nn + col0 + cc];
        }
        // Stage S^T half 0: sST[c][k] for k=0..255 (half a k-row per thread)
        {
            const float* srow = Sbt + (size_t)skrow * Nn + col0 + scol0;
            float4 v0 = *reinterpret_cast<const float4*>(srow);
            float4 v1 = *reinterpret_cast<const float4*>(srow + 4);
            float* d = sST + skrow;
            d[(scol0 + 0) * PITCH_SST] = v0.x; d[(scol0 + 1) * PITCH_SST] = v0.y;
            d[(scol0 + 2) * PITCH_SST] = v0.z; d[(scol0 + 3) * PITCH_SST] = v0.w;
            d[(scol0 + 4) * PITCH_SST] = v1.x; d[(scol0 + 5) * PITCH_SST] = v1.y;
            d[(scol0 + 6) * PITCH_SST] = v1.z; d[(scol0 + 7) * PITCH_SST] = v1.w;
        }
        __syncthreads();                 // sST half0 + sV.x ready
        mbar_wait(mbar0, ph0); ph0 ^= 1u;

        unsigned long long acc[RPT][4];
#pragma unroll
        for (int r = 0; r < RPT; ++r)
#pragma unroll
            for (int ci = 0; ci < 4; ++ci) acc[r][ci] = 0ull;

        for (int c = 0; c < NCHUNK; ++c) {
            const int buf = c & 1, nb = buf ^ 1;
            // prefetch chunk c+1 into nb (nb freed by the sync at end of c-1)
            if (c < NCHUNK - 1 && tid == 0) {
                uint32_t mb = nb ? mbar1 : mbar0;
                uint32_t ds = nb ? st_smem1 : st_smem0;
                mbar_expect_tx(mb, CHUNK_BYTES);
                bulk_copy(ds, gst + (size_t)(c + 1) * CHUNK_FLOATS, CHUNK_BYTES, mb);
            }
            // compute chunk c: this kg-group's k-quarter (8 k's = 2 s-steps)
            {
                const float* slot = sm + OFF_STATE + buf * CHUNK_FLOATS + R0 * CPITCH;
                const int kkb = ((c & 7) << 5) + (kg << 3);   // sST local k base
#pragma unroll
                for (int s = 0; s < 2; ++s) {
                    const int kloc = (kg << 3) + (s << 2);    // within chunk row
                    const int kk   = kkb + (s << 2);
                    ulonglong2 bb[4];
#pragma unroll
                    for (int ci = 0; ci < 4; ++ci)
                        bb[ci] = *reinterpret_cast<const ulonglong2*>(
                            sST + (cgp + 4 * ci) * PITCH_SST + kk);
#pragma unroll
                    for (int r = 0; r < RPT; ++r) {
                        const ulonglong2 sv = *reinterpret_cast<const ulonglong2*>(
                            slot + r * CPITCH + kloc);
#pragma unroll
                        for (int ci = 0; ci < 4; ++ci) {
                            acc[r][ci] = ffma2(sv.x, bb[ci].x, acc[r][ci]);
                            acc[r][ci] = ffma2(sv.y, bb[ci].y, acc[r][ci]);
                        }
                    }
                }
            }
            // mid-t: restage S^T half 1 (needs all reads of half 0 done)
            if (c == 7) {
                __syncthreads();
                const float* srow = Sbt + (size_t)(SST_HALF + skrow) * Nn + col0 + scol0;
                float4 v0 = *reinterpret_cast<const float4*>(srow);
                float4 v1 = *reinterpret_cast<const float4*>(srow + 4);
                float* d = sST + skrow;
                d[(scol0 + 0) * PITCH_SST] = v0.x; d[(scol0 + 1) * PITCH_SST] = v0.y;
                d[(scol0 + 2) * PITCH_SST] = v0.z; d[(scol0 + 3) * PITCH_SST] = v0.w;
                d[(scol0 + 4) * PITCH_SST] = v1.x; d[(scol0 + 5) * PITCH_SST] = v1.y;
                d[(scol0 + 6) * PITCH_SST] = v1.z; d[(scol0 + 7) * PITCH_SST] = v1.w;
            }
            __syncthreads();             // buffer reuse + half1 visibility
            if (c < NCHUNK - 1) {
                if (nb) { mbar_wait(mbar1, ph1); ph1 ^= 1u; }
                else    { mbar_wait(mbar0, ph0); ph0 ^= 1u; }
            }
        }

        // Sequential reduction of the 4 k-group partials (sYp aliases sST)
        if (kg == 3) {
#pragma unroll
            for (int r = 0; r < RPT; ++r)
#pragma unroll
                for (int ci = 0; ci < 4; ++ci)
                    sYp[(R0 + r) * PITCH_YP + cgp + 4 * ci] = upsum(acc[r][ci]);
        }
        __syncthreads();
        if (kg == 2) {
#pragma unroll
            for (int r = 0; r < RPT; ++r)
#pragma unroll
                for (int ci = 0; ci < 4; ++ci)
                    sYp[(R0 + r) * PITCH_YP + cgp + 4 * ci] += upsum(acc[r][ci]);
        }
        __syncthreads();
        if (kg == 1) {
#pragma unroll
            for (int r = 0; r < RPT; ++r)
#pragma unroll
                for (int ci = 0; ci < 4; ++ci)
                    sYp[(R0 + r) * PITCH_YP + cgp + 4 * ci] += upsum(acc[r][ci]);
        }
        __syncthreads();
        if (kg == 0) {
#pragma unroll
            for (int r = 0; r < RPT; ++r) {
                int row = R0 + r;
                int j = (row < 96) ? (32 + row) : (96 + row);
#pragma unroll
                for (int ci = 0; ci < 4; ++ci) {
                    int cc = cgp + 4 * ci;
                    sV[cc * PITCH_V + j] =
                        upsum(acc[r][ci]) + sYp[row * PITCH_YP + cc];
                }
            }
        }
        __syncthreads();

        // Phase 2: pre[h,c] = bias[h] + sum_j sW[h][j] * sV[c][j]
        unsigned long long pa[2] = {0ull, 0ull};
        {
            const float* vp = sV + cc2 * PITCH_V;
#pragma unroll 4
            for (int j = 0; j < NV; j += 4) {
                ulonglong2 v = *reinterpret_cast<const ulonglong2*>(vp + j);
#pragma unroll
                for (int i = 0; i < 2; ++i) {
                    ulonglong2 w = *reinterpret_cast<const ulonglong2*>(
                        sW + (h2 + 32 * i) * NV + j);
                    pa[i] = ffma2(w.x, v.x, pa[i]);
                    pa[i] = ffma2(w.y, v.y, pa[i]);
                }
            }
        }
        float zv[2];
#pragma unroll
        for (int i = 0; i < 2; ++i)
            zv[i] = tanhf(sbias[h2 + 32 * i] + upsum(pa[i]));

        // State shift for t+1 (column-local STG into padded layout)
        {
            float* gnxt = &g_state[nxt][b][kc0][0][0];
#pragma unroll
            for (int it = 0; it < 9; ++it) {
                int i = tid + it * NTHREADS;
                int r = i >> 4, cc = i & 15;
                int j = (r < 96) ? r : (r + 32);
                gnxt[r * CPITCH + cmb + cc] = sV[cc * PITCH_V + j];
            }
        }
        __syncthreads();   // all reads of z(t-1) done before overwrite

        // write z(t) -> out + sV z-region
#pragma unroll
        for (int i = 0; i < 2; ++i) {
            int h = h2 + 32 * i;
            out[(((size_t)b * Tn + t) * Hn + h) * Nn + col0 + cc2] = zv[i];
            sV[cc2 * PITCH_V + 128 + h] = zv[i];
        }

        grid_barrier(&lsense);   // barriers #2..#65
    }

    grid_barrier(&lsense);       // barrier #66 (even parity per launch)
}

extern "C" void kernel_launch(void* const* d_in, const int* in_sizes, int n_in,
                              void* d_out, int out_size) {
    const float* x     = (const float*)d_in[0];
    const float* z0    = (const float*)d_in[1];
    const float* S     = (const float*)d_in[2];
    const float* aW    = (const float*)d_in[3];
    const float* bW    = (const float*)d_in[4];
    const float* xBias = (const float*)d_in[5];
    const float* zBias = (const float*)d_in[6];
    float* out = (float*)d_out;

    cudaFuncSetAttribute(hs_db_kernel,
                         cudaFuncAttributeMaxDynamicSharedMemorySize, SMEM_BYTES);
    hs_db_kernel<<<NCTAS, NTHREADS, SMEM_BYTES>>>(x, z0, S, aW, bW, xBias, zBias, out);
}

// round 13
// speedup vs baseline: 1.5559x; 1.5559x over previous
#include <cuda_runtime.h>
#include <cstdint>

// Problem constants
#define Bn 4
#define Tn 64
#define Fn 32
#define Nn 512
#define Hn 64
#define SROWS 288
#define COLS_PER_CTA 16
#define CTAS_PER_B 32
#define NCTAS (Bn * CTAS_PER_B)   // 128 CTAs, 1/SM
#define NTHREADS 256
#define MB 32                     // k-chunk width
#define NCHUNK (Nn / MB)          // 16

#define CPITCH 36                 // chunk row pitch
#define PITCH_SST 260             // S^T half pitch
#define SST_HALF 256
#define PITCH_V  388
#define NV       384

#define CHUNK_FLOATS (SROWS * CPITCH)      // 10368
#define CHUNK_BYTES  (CHUNK_FLOATS * 4)    // 41472

// smem layout (float offsets)
#define OFF_W      0                        // 24576
#define OFF_BIAS   24576                    // 64
#define OFF_MBAR   24640                    // 4
#define OFF_STATE  24644                    // 2*10368 = 20736
#define OFF_SST    45380                    // 16*260 = 4160
#define OFF_V      49540                    // 16*388 = 6208
#define SMEM_FLOATS 55748
#define SMEM_BYTES  (SMEM_FLOATS * 4)       // 222992

// Persistent global state: chunk-major, rows pre-padded to CPITCH floats.
__device__ __align__(16) float g_state[2][Bn][NCHUNK][SROWS][CPITCH];
__device__ unsigned g_count = 0;
__device__ unsigned g_sense = 0;

__device__ __forceinline__ void grid_barrier(unsigned* lsense) {
    __syncthreads();
    if (threadIdx.x == 0) {
        __threadfence();
        unsigned s = (*lsense) ^ 1u;
        *lsense = s;
        unsigned old = atomicAdd(&g_count, 1u);
        if (old == NCTAS - 1u) {
            atomicExch(&g_count, 0u);
            __threadfence();
            atomicExch(&g_sense, s);
        } else {
            while (atomicAdd(&g_sense, 0u) != s) { __nanosleep(64); }
            __threadfence();
        }
    }
    __syncthreads();
}

__device__ __forceinline__ unsigned long long ffma2(unsigned long long a,
                                                    unsigned long long b,
                                                    unsigned long long c) {
    unsigned long long d;
    asm("fma.rn.f32x2 %0, %1, %2, %3;" : "=l"(d) : "l"(a), "l"(b), "l"(c));
    return d;
}
__device__ __forceinline__ float upsum(unsigned long long p) {
    float lo, hi;
    asm("mov.b64 {%0, %1}, %2;" : "=f"(lo), "=f"(hi) : "l"(p));
    return lo + hi;
}
__device__ __forceinline__ float to_tf32(float v) {
    float r;
    asm("cvt.rna.tf32.f32 %0, %1;" : "=f"(r) : "f"(v));
    return r;
}

// mma.sync m16n8k8 tf32 (sm_80+ PTX; compiles at compute_103)
__device__ __forceinline__ void mma_tf32(float& d0, float& d1, float& d2, float& d3,
                                         uint32_t a0, uint32_t a1, uint32_t a2, uint32_t a3,
                                         uint32_t b0, uint32_t b1) {
    asm volatile(
        "mma.sync.aligned.m16n8k8.row.col.f32.tf32.tf32.f32 "
        "{%0,%1,%2,%3}, {%4,%5,%6,%7}, {%8,%9}, {%0,%1,%2,%3};"
        : "+f"(d0), "+f"(d1), "+f"(d2), "+f"(d3)
        : "r"(a0), "r"(a1), "r"(a2), "r"(a3), "r"(b0), "r"(b1));
}

// mbarrier helpers
__device__ __forceinline__ void mbar_init(uint32_t addr, uint32_t count) {
    asm volatile("mbarrier.init.shared.b64 [%0], %1;" :: "r"(addr), "r"(count) : "memory");
}
__device__ __forceinline__ void mbar_expect_tx(uint32_t addr, uint32_t bytes) {
    asm volatile("mbarrier.arrive.expect_tx.shared.b64 _, [%0], %1;"
                 :: "r"(addr), "r"(bytes) : "memory");
}
__device__ __forceinline__ void mbar_wait(uint32_t addr, uint32_t parity) {
    uint32_t done;
    asm volatile(
        "{\n\t.reg .pred p;\n\t"
        "mbarrier.try_wait.parity.acquire.cta.shared::cta.b64 p, [%1], %2;\n\t"
        "selp.b32 %0, 1, 0, p;\n\t}"
        : "=r"(done) : "r"(addr), "r"(parity) : "memory");
    if (!done) {
        asm volatile(
            "{\n\t.reg .pred P1;\n\t"
            "WL_%=:\n\t"
            "mbarrier.try_wait.parity.acquire.cta.shared::cta.b64 P1, [%0], %1, 0x989680;\n\t"
            "@P1 bra.uni WD_%=;\n\t"
            "bra.uni WL_%=;\n\t"
            "WD_%=:\n\t}"
            :: "r"(addr), "r"(parity) : "memory");
    }
}
__device__ __forceinline__ void bulk_copy(uint32_t dst_smem, const void* src, uint32_t bytes,
                                          uint32_t mbar) {
    asm volatile(
        "cp.async.bulk.shared::cta.global.mbarrier::complete_tx::bytes [%0], [%1], %2, [%3];"
        :: "r"(dst_smem), "l"(src), "r"(bytes), "r"(mbar) : "memory");
}

__global__ void __launch_bounds__(NTHREADS, 1)
hs_db_kernel(const float* __restrict__ x,      // (B,T,F,N)
             const float* __restrict__ z0,     // (B,H,N)
             const float* __restrict__ S,      // (B,T,1,N,N)
             const float* __restrict__ aW,     // (H,1,K,F)
             const float* __restrict__ bW,     // (H,1,K,H)
             const float* __restrict__ xBias,  // (H,1)
             const float* __restrict__ zBias,  // (H,1)
             float* __restrict__ out)          // (B,T,H,N)
{
    extern __shared__ float sm[];
    float* sW    = sm + OFF_W;
    float* sbias = sm + OFF_BIAS;
    float* sST   = sm + OFF_SST;    // [16][260] S^T half, tf32-rounded
    float* sV    = sm + OFF_V;

    const int tid  = threadIdx.x;
    const int b    = blockIdx.x / CTAS_PER_B;
    const int col0 = (blockIdx.x % CTAS_PER_B) * COLS_PER_CTA;
    const int kc0  = col0 >> 5;           // this CTA's write chunk
    const int cmb  = col0 & 31;           // 0 or 16 within chunk

    // mma mapping
    const int wid  = tid >> 5;            // warp 0..7; m-groups {wid, wid+8, wid+16<18}
    const int lane = tid & 31;
    const int gid  = lane >> 2;           // groupID 0..7
    const int tid4 = lane & 3;            // threadID_in_group
    // phase-2 mapping
    const int hq  = tid >> 4;             // 0..15; h in {hq,hq+16,hq+32,hq+48}
    const int cc2 = tid & 15;

    const uint32_t smem_u32 = (uint32_t)__cvta_generic_to_shared(sm);
    const uint32_t mbar0 = smem_u32 + OFF_MBAR * 4;
    const uint32_t mbar1 = mbar0 + 8;
    const uint32_t st_smem0 = smem_u32 + OFF_STATE * 4;
    const uint32_t st_smem1 = st_smem0 + CHUNK_BYTES;

    if (tid == 0) { mbar_init(mbar0, 1); mbar_init(mbar1, 1); }

    // Load fused weights once: sW[h][0..127]=aW[h], [128..383]=bW[h]
    for (int i = tid; i < Hn * 128; i += NTHREADS) {
        int h = i >> 7, j = i & 127;
        sW[h * NV + j] = aW[i];
    }
    for (int i = tid; i < Hn * 256; i += NTHREADS) {
        int h = i >> 8, j = i & 255;
        sW[h * NV + 128 + j] = bW[i];
    }
    if (tid < Hn) sbias[tid] = xBias[tid] + zBias[tid];

    // Init: zero this CTA's state columns; sV z-region <- z0
    for (int i = tid; i < SROWS * COLS_PER_CTA; i += NTHREADS) {
        int r = i >> 4, cc = i & 15;
        g_state[0][b][kc0][r][cmb + cc] = 0.0f;
    }
    for (int i = tid; i < Hn * COLS_PER_CTA; i += NTHREADS) {
        int g = i >> 4, cc = i & 15;
        sV[cc * PITCH_V + 128 + g] = z0[(b * Hn + g) * Nn + col0 + cc];
    }

    unsigned lsense = 0;
    unsigned ph0 = 0, ph1 = 0;
    grid_barrier(&lsense);   // barrier #1

    for (int t = 0; t < Tn; ++t) {
        const int cur = t & 1;
        const int nxt = cur ^ 1;
        const float* Sbt = S + (size_t)(b * Tn + t) * Nn * Nn;
        const float* xbt = x + (size_t)(b * Tn + t) * Fn * Nn;
        const float* gst = &g_state[cur][b][0][0][0];

        // prologue: launch TMA for chunk 0 immediately
        if (tid == 0) {
            mbar_expect_tx(mbar0, CHUNK_BYTES);
            bulk_copy(st_smem0, gst, CHUNK_BYTES, mbar0);
        }

        // Stage x(t) -> sV[cc][0..31]
        for (int i = tid; i < Fn * 16; i += NTHREADS) {
            int f = i >> 4, cc = i & 15;
            sV[cc * PITCH_V + f] = xbt[f * Nn + col0 + cc];
        }
        // Stage S^T half 0 (tf32-rounded): sST[c][k] for k=0..255
        {
            const float* srow = Sbt + (size_t)tid * Nn + col0;
            float4 v0 = *reinterpret_cast<const float4*>(srow);
            float4 v1 = *reinterpret_cast<const float4*>(srow + 4);
            float4 v2 = *reinterpret_cast<const float4*>(srow + 8);
            float4 v3 = *reinterpret_cast<const float4*>(srow + 12);
            float* d = sST + tid;
            d[0 * PITCH_SST]  = to_tf32(v0.x); d[1 * PITCH_SST]  = to_tf32(v0.y);
            d[2 * PITCH_SST]  = to_tf32(v0.z); d[3 * PITCH_SST]  = to_tf32(v0.w);
            d[4 * PITCH_SST]  = to_tf32(v1.x); d[5 * PITCH_SST]  = to_tf32(v1.y);
            d[6 * PITCH_SST]  = to_tf32(v1.z); d[7 * PITCH_SST]  = to_tf32(v1.w);
            d[8 * PITCH_SST]  = to_tf32(v2.x); d[9 * PITCH_SST]  = to_tf32(v2.y);
            d[10 * PITCH_SST] = to_tf32(v2.z); d[11 * PITCH_SST] = to_tf32(v2.w);
            d[12 * PITCH_SST] = to_tf32(v3.x); d[13 * PITCH_SST] = to_tf32(v3.y);
            d[14 * PITCH_SST] = to_tf32(v3.z); d[15 * PITCH_SST] = to_tf32(v3.w);
        }
        __syncthreads();                 // sST half0 + sV.x ready
        mbar_wait(mbar0, ph0); ph0 ^= 1u;

        // acc[mgi][nt][4] — full-K accumulators in registers
        float acc[3][2][4];
#pragma unroll
        for (int i = 0; i < 3; ++i)
#pragma unroll
            for (int n = 0; n < 2; ++n)
#pragma unroll
                for (int q = 0; q < 4; ++q) acc[i][n][q] = 0.0f;

        for (int c = 0; c < NCHUNK; ++c) {
            const int buf = c & 1, nb = buf ^ 1;
            if (c < NCHUNK - 1 && tid == 0) {
                uint32_t mb = nb ? mbar1 : mbar0;
                uint32_t ds = nb ? st_smem1 : st_smem0;
                mbar_expect_tx(mb, CHUNK_BYTES);
                bulk_copy(ds, gst + (size_t)(c + 1) * CHUNK_FLOATS, CHUNK_BYTES, mb);
            }
            // compute chunk c: 4 k8-steps
            {
                const float* slot = sm + OFF_STATE + buf * CHUNK_FLOATS;
                const int kkb = ((c & 7) << 5);   // sST local k base for this chunk
#pragma unroll
                for (int ks = 0; ks < 4; ++ks) {
                    const int kl = (ks << 3) + tid4;      // chunk-local k col
                    const int kk = kkb + (ks << 3) + tid4;
                    // B fragments for n-tiles 0,1: b[nt][0..1]
                    uint32_t bfr[2][2];
#pragma unroll
                    for (int nt = 0; nt < 2; ++nt) {
                        const float* bp = sST + (8 * nt + gid) * PITCH_SST + kk;
                        bfr[nt][0] = __float_as_uint(bp[0]);
                        bfr[nt][1] = __float_as_uint(bp[4]);
                    }
#pragma unroll
                    for (int i = 0; i < 3; ++i) {
                        const int mg = wid + 8 * i;
                        if (mg < 18) {
                            const float* ap = slot + (16 * mg + gid) * CPITCH + kl;
                            uint32_t a0 = __float_as_uint(ap[0]);
                            uint32_t a1 = __float_as_uint(ap[8 * CPITCH]);
                            uint32_t a2 = __float_as_uint(ap[4]);
                            uint32_t a3 = __float_as_uint(ap[8 * CPITCH + 4]);
                            mma_tf32(acc[i][0][0], acc[i][0][1], acc[i][0][2], acc[i][0][3],
                                     a0, a1, a2, a3, bfr[0][0], bfr[0][1]);
                            mma_tf32(acc[i][1][0], acc[i][1][1], acc[i][1][2], acc[i][1][3],
                                     a0, a1, a2, a3, bfr[1][0], bfr[1][1]);
                        }
                    }
                }
            }
            // mid-t: restage S^T half 1
            if (c == 7) {
                __syncthreads();
                const float* srow = Sbt + (size_t)(SST_HALF + tid) * Nn + col0;
                float4 v0 = *reinterpret_cast<const float4*>(srow);
                float4 v1 = *reinterpret_cast<const float4*>(srow + 4);
                float4 v2 = *reinterpret_cast<const float4*>(srow + 8);
                float4 v3 = *reinterpret_cast<const float4*>(srow + 12);
                float* d = sST + tid;
                d[0 * PITCH_SST]  = to_tf32(v0.x); d[1 * PITCH_SST]  = to_tf32(v0.y);
                d[2 * PITCH_SST]  = to_tf32(v0.z); d[3 * PITCH_SST]  = to_tf32(v0.w);
                d[4 * PITCH_SST]  = to_tf32(v1.x); d[5 * PITCH_SST]  = to_tf32(v1.y);
                d[6 * PITCH_SST]  = to_tf32(v1.z); d[7 * PITCH_SST]  = to_tf32(v1.w);
                d[8 * PITCH_SST]  = to_tf32(v2.x); d[9 * PITCH_SST]  = to_tf32(v2.y);
                d[10 * PITCH_SST] = to_tf32(v2.z); d[11 * PITCH_SST] = to_tf32(v2.w);
                d[12 * PITCH_SST] = to_tf32(v3.x); d[13 * PITCH_SST] = to_tf32(v3.y);
                d[14 * PITCH_SST] = to_tf32(v3.z); d[15 * PITCH_SST] = to_tf32(v3.w);
            }
            __syncthreads();             // buffer reuse + half1 visibility
            if (c < NCHUNK - 1) {
                if (nb) { mbar_wait(mbar1, ph1); ph1 ^= 1u; }
                else    { mbar_wait(mbar0, ph0); ph0 ^= 1u; }
            }
        }

        // Write Y (acc) into transposed sV: row<96 -> j=32+row ; row>=96 -> j=96+row
#pragma unroll
        for (int i = 0; i < 3; ++i) {
            const int mg = wid + 8 * i;
            if (mg < 18) {
                const int r_lo = 16 * mg + gid;
                const int r_hi = r_lo + 8;
                const int j_lo = (r_lo < 96) ? (32 + r_lo) : (96 + r_lo);
                const int j_hi = (r_hi < 96) ? (32 + r_hi) : (96 + r_hi);
#pragma unroll
                for (int nt = 0; nt < 2; ++nt) {
                    const int cl = 8 * nt + 2 * tid4;
                    sV[cl * PITCH_V + j_lo]       = acc[i][nt][0];
                    sV[(cl + 1) * PITCH_V + j_lo] = acc[i][nt][1];
                    sV[cl * PITCH_V + j_hi]       = acc[i][nt][2];
                    sV[(cl + 1) * PITCH_V + j_hi] = acc[i][nt][3];
                }
            }
        }
        __syncthreads();

        // Phase 2: pre[h,c] = bias[h] + sum_j sW[h][j] * sV[c][j]
        unsigned long long pa[4] = {0ull, 0ull, 0ull, 0ull};
        {
            const float* vp = sV + cc2 * PITCH_V;
#pragma unroll 4
            for (int j = 0; j < NV; j += 4) {
                ulonglong2 v = *reinterpret_cast<const ulonglong2*>(vp + j);
#pragma unroll
                for (int i = 0; i < 4; ++i) {
                    ulonglong2 w = *reinterpret_cast<const ulonglong2*>(
                        sW + (hq + 16 * i) * NV + j);
                    pa[i] = ffma2(w.x, v.x, pa[i]);
                    pa[i] = ffma2(w.y, v.y, pa[i]);
                }
            }
        }
        float zv[4];
#pragma unroll
        for (int i = 0; i < 4; ++i)
            zv[i] = tanhf(sbias[hq + 16 * i] + upsum(pa[i]));

        // State shift for t+1 (column-local STG, tf32-rounded for the MMA A side)
        {
            float* gnxt = &g_state[nxt][b][kc0][0][0];
#pragma unroll
            for (int it = 0; it < 18; ++it) {
                int i = tid + it * NTHREADS;
                int r = i >> 4, cc = i & 15;
                int j = (r < 96) ? r : (r + 32);
                gnxt[r * CPITCH + cmb + cc] = to_tf32(sV[cc * PITCH_V + j]);
            }
        }
        __syncthreads();   // all reads of z(t-1) done before overwrite

        // write z(t) -> out + sV z-region
#pragma unroll
        for (int i = 0; i < 4; ++i) {
            int h = hq + 16 * i;
            out[(((size_t)b * Tn + t) * Hn + h) * Nn + col0 + cc2] = zv[i];
            sV[cc2 * PITCH_V + 128 + h] = zv[i];
        }

        grid_barrier(&lsense);   // barriers #2..#65
    }

    grid_barrier(&lsense);       // barrier #66 (even parity per launch)
}

extern "C" void kernel_launch(void* const* d_in, const int* in_sizes, int n_in,
                              void* d_out, int out_size) {
    const float* x     = (const float*)d_in[0];
    const float* z0    = (const float*)d_in[1];
    const float* S     = (const float*)d_in[2];
    const float* aW    = (const float*)d_in[3];
    const float* bW    = (const float*)d_in[4];
    const float* xBias = (const float*)d_in[5];
    const float* zBias = (const float*)d_in[6];
    float* out = (float*)d_out;

    cudaFuncSetAttribute(hs_db_kernel,
                         cudaFuncAttributeMaxDynamicSharedMemorySize, SMEM_BYTES);
    hs_db_kernel<<<NCTAS, NTHREADS, SMEM_BYTES>>>(x, z0, S, aW, bW, xBias, zBias, out);
}